// round 8
// baseline (speedup 1.0000x reference)
#include <cuda_runtime.h>
#include <math_constants.h>

// x:    (16, 64, 512, 512) float32
// mask: (16, 1, 512, 512) int32
// out:  (16, 64) float32
#define NB 16
#define NC 64
#define HW (512 * 512)                 // 262144
#define CHUNKS 16                      // chunks per (b,c) row
#define THREADS 256
#define CG 4                           // channels per block
#define F4_PER_CHUNK (HW / 4 / CHUNKS) // 4096 float4 per chunk
#define ITERS (F4_PER_CHUNK / THREADS) // 16 float4 per thread per channel
#define U4_PER_CHUNK (F4_PER_CHUNK / 32)  // 128 bitmask uint4 per chunk
#define NROWS (NB * NC)                // 1024
#define NGRP (NB * (NC / CG))          // 256 row-groups

// All scratch is either overwritten every launch (g_partial), self-resetting
// (g_ctr), or monotone & input-determined (g_nonempty) => graph-replay safe.
__device__ float g_partial[NROWS * CHUNKS];
__device__ int   g_ctr[NGRP];           // count to CHUNKS, last block resets
__device__ int   g_nonempty[NB];        // 0-init; atomicOr only

__global__ void __launch_bounds__(THREADS)
fused_kernel(const float4* __restrict__ x, const int4* __restrict__ mask4,
             float* __restrict__ out) {
    int blk  = blockIdx.x;              // = (b*16 + cg)*16 + chunk
    int t    = threadIdx.x;
    int lane = t & 31;
    int wid  = t >> 5;

    int chunk = blk & (CHUNKS - 1);
    int cg    = (blk >> 4) & (NC / CG - 1);
    int b     = blk >> 8;
    int grp   = blk >> 4;               // b*16 + cg
    int rowbase = b * NC + cg * CG;

    __shared__ uint4 sbits[U4_PER_CHUNK];   // 2 KiB, R5-proven layout
    __shared__ float smax[CG * (THREADS / 32)];
    __shared__ bool  slast;

    // ---- Self-pack this chunk's mask (16 int4/thread, ballots -> smem) ----
    const int4* mr = mask4 + (size_t)b * (HW / 4)
                           + (size_t)chunk * F4_PER_CHUNK;
    unsigned any = 0;
#pragma unroll
    for (int i = 0; i < ITERS; i++) {
        int4 mv = __ldg(mr + i * THREADS + t);
        unsigned w0 = __ballot_sync(0xffffffffu, mv.x != 0);
        unsigned w1 = __ballot_sync(0xffffffffu, mv.y != 0);
        unsigned w2 = __ballot_sync(0xffffffffu, mv.z != 0);
        unsigned w3 = __ballot_sync(0xffffffffu, mv.w != 0);
        any |= (w0 | w1 | w2 | w3);
        if (lane == 0)
            sbits[i * (THREADS / 32) + wid] = make_uint4(w0, w1, w2, w3);
    }
    int bany = __syncthreads_or((int)(any != 0));   // also publishes sbits
    if (t == 0 && bany) atomicOr(&g_nonempty[b], 1);

    // ---- Stream CG channels of x through the roofline body ----
    const float4* xb = x + (size_t)rowbase * (HW / 4)
                         + (size_t)chunk * F4_PER_CHUNK;
    for (int j = 0; j < CG; j++) {
        const float4* xr = xb + (size_t)j * (HW / 4);
        float vmax = -CUDART_INF_F;
#pragma unroll
        for (int i = 0; i < ITERS; i++) {
            int idx = i * THREADS + t;
            float4 xv = __ldg(xr + idx);
            uint4  w  = sbits[idx >> 5];        // warp-broadcast LDS.128
            vmax = fmaxf(vmax, ((w.x >> lane) & 1u) ? xv.x : -CUDART_INF_F);
            vmax = fmaxf(vmax, ((w.y >> lane) & 1u) ? xv.y : -CUDART_INF_F);
            vmax = fmaxf(vmax, ((w.z >> lane) & 1u) ? xv.z : -CUDART_INF_F);
            vmax = fmaxf(vmax, ((w.w >> lane) & 1u) ? xv.w : -CUDART_INF_F);
        }
#pragma unroll
        for (int o = 16; o; o >>= 1)
            vmax = fmaxf(vmax, __shfl_xor_sync(0xffffffffu, vmax, o));
        if (lane == 0) smax[j * (THREADS / 32) + wid] = vmax;
    }
    __syncthreads();

    // ---- Per-block: reduce 8 warp-partials per channel, write 4 partials ----
    if (t < CG * (THREADS / 32)) {      // 32 threads: j = t>>3, warp w = t&7
        float v = smax[t];
#pragma unroll
        for (int o = 4; o; o >>= 1)
            v = fmaxf(v, __shfl_xor_sync(0xffffffffu, v, o));
        if ((t & 7) == 0)
            g_partial[(rowbase + (t >> 3)) * CHUNKS + chunk] = v;
    }
    __threadfence();                    // all threads: order partials device-wide
    __syncthreads();

    if (t == 0) {
        int old = atomicAdd(&g_ctr[grp], 1);
        slast = (old == CHUNKS - 1);
    }
    __syncthreads();

    // ---- Last block of the row-group: reduce 4x16 partials, fixup, out ----
    if (slast && t < CG * CHUNKS) {     // 64 threads: j = t>>4, k = t&15
        int j = t >> 4;
        float v = g_partial[(rowbase + j) * CHUNKS + (t & 15)];
#pragma unroll
        for (int o = 8; o; o >>= 1)
            v = fmaxf(v, __shfl_xor_sync(0xffffffffu, v, o));
        if ((t & 15) == 0)
            out[rowbase + j] = g_nonempty[b] ? v : 0.0f;
        if (t == 0) g_ctr[grp] = 0;     // reset for next graph replay
    }
}

extern "C" void kernel_launch(void* const* d_in, const int* in_sizes, int n_in,
                              void* d_out, int out_size) {
    const float4* x     = (const float4*)d_in[0];
    const int4*   mask4 = (const int4*)d_in[1];
    float*        out   = (float*)d_out;

    fused_kernel<<<NB * (NC / CG) * CHUNKS, THREADS>>>(x, mask4, out);
}

// round 9
// speedup vs baseline: 1.0209x; 1.0209x over previous
#include <cuda_runtime.h>
#include <math_constants.h>

// x:    (16, 64, 512, 512) float32
// mask: (16, 1, 512, 512) int32
// out:  (16, 64) float32
#define NB 16
#define NC 64
#define HW (512 * 512)                 // 262144
#define CHUNKS 16                      // chunks per (b,c) row
#define THREADS 256
#define CG 4                           // channels per block
#define F4_PER_CHUNK (HW / 4 / CHUNKS) // 4096 float4 per chunk
#define ITERS (F4_PER_CHUNK / THREADS) // 16 float4 per thread per channel
#define NROWS (NB * NC)                // 1024
#define NGRP (NB * (NC / CG))          // 256 row-groups

// Scratch: g_partial fully overwritten each launch; g_ctr self-resetting;
// g_nonempty monotone OR of input-determined value => graph-replay safe.
__device__ float g_partial[NROWS * CHUNKS];
__device__ int   g_ctr[NGRP];
__device__ int   g_nonempty[NB];

__global__ void __launch_bounds__(THREADS)
fused_kernel(const float4* __restrict__ x, const int4* __restrict__ mask4,
             float* __restrict__ out) {
    int blk  = blockIdx.x;              // = (b*16 + cg)*16 + chunk
    int t    = threadIdx.x;
    int lane = t & 31;
    int wid  = t >> 5;

    int chunk = blk & (CHUNKS - 1);
    int b     = blk >> 8;
    int grp   = blk >> 4;               // b*16 + cg
    int cg    = grp & (NC / CG - 1);
    int rowbase = b * NC + cg * CG;

    __shared__ float smax[CG * (THREADS / 32)];
    __shared__ bool  slast;

    // ---- Private mask pack: this thread's 64 positions -> 2 registers ----
    // Thread t's float4 idx set {i*256+t} matches the mask int4 at same idx.
    const int4* mr = mask4 + (size_t)b * (HW / 4)
                           + (size_t)chunk * F4_PER_CHUNK;
    unsigned bits0 = 0, bits1 = 0;
#pragma unroll
    for (int i = 0; i < ITERS; i++) {
        int4 mv = __ldg(mr + i * THREADS + t);
        unsigned nib = (unsigned)(mv.x != 0)
                     | ((unsigned)(mv.y != 0) << 1)
                     | ((unsigned)(mv.z != 0) << 2)
                     | ((unsigned)(mv.w != 0) << 3);
        if (i < 8) bits0 |= nib << (4 * i);
        else       bits1 |= nib << (4 * (i - 8));
    }
    int bany = __syncthreads_or((int)((bits0 | bits1) != 0));
    if (t == 0 && bany) atomicOr(&g_nonempty[b], 1);

    // ---- Stream CG channels, j-inner for 4x load batching ----
    const float4* xb = x + (size_t)rowbase * (HW / 4)
                         + (size_t)chunk * F4_PER_CHUNK;
    float acc0 = -CUDART_INF_F, acc1 = -CUDART_INF_F;
    float acc2 = -CUDART_INF_F, acc3 = -CUDART_INF_F;
#pragma unroll 4
    for (int i = 0; i < ITERS; i++) {
        unsigned nib = ((i < 8) ? (bits0 >> (4 * i))
                                : (bits1 >> (4 * (i - 8)))) & 0xFu;
        int idx = i * THREADS + t;
        float4 x0 = __ldg(xb + 0 * (HW / 4) + idx);
        float4 x1 = __ldg(xb + 1 * (HW / 4) + idx);
        float4 x2 = __ldg(xb + 2 * (HW / 4) + idx);
        float4 x3 = __ldg(xb + 3 * (HW / 4) + idx);
        bool m0 = nib & 1u, m1 = nib & 2u, m2 = nib & 4u, m3 = nib & 8u;
        acc0 = fmaxf(acc0, m0 ? x0.x : -CUDART_INF_F);
        acc0 = fmaxf(acc0, m1 ? x0.y : -CUDART_INF_F);
        acc0 = fmaxf(acc0, m2 ? x0.z : -CUDART_INF_F);
        acc0 = fmaxf(acc0, m3 ? x0.w : -CUDART_INF_F);
        acc1 = fmaxf(acc1, m0 ? x1.x : -CUDART_INF_F);
        acc1 = fmaxf(acc1, m1 ? x1.y : -CUDART_INF_F);
        acc1 = fmaxf(acc1, m2 ? x1.z : -CUDART_INF_F);
        acc1 = fmaxf(acc1, m3 ? x1.w : -CUDART_INF_F);
        acc2 = fmaxf(acc2, m0 ? x2.x : -CUDART_INF_F);
        acc2 = fmaxf(acc2, m1 ? x2.y : -CUDART_INF_F);
        acc2 = fmaxf(acc2, m2 ? x2.z : -CUDART_INF_F);
        acc2 = fmaxf(acc2, m3 ? x2.w : -CUDART_INF_F);
        acc3 = fmaxf(acc3, m0 ? x3.x : -CUDART_INF_F);
        acc3 = fmaxf(acc3, m1 ? x3.y : -CUDART_INF_F);
        acc3 = fmaxf(acc3, m2 ? x3.z : -CUDART_INF_F);
        acc3 = fmaxf(acc3, m3 ? x3.w : -CUDART_INF_F);
    }

    // ---- Warp reduce each channel accumulator ----
    float a[CG] = {acc0, acc1, acc2, acc3};
#pragma unroll
    for (int j = 0; j < CG; j++) {
        float v = a[j];
#pragma unroll
        for (int o = 16; o; o >>= 1)
            v = fmaxf(v, __shfl_xor_sync(0xffffffffu, v, o));
        if (lane == 0) smax[j * (THREADS / 32) + wid] = v;
    }
    __syncthreads();

    // ---- Per-block: reduce 8 warp-partials per channel, write 4 partials ----
    if (t < CG * (THREADS / 32)) {      // 32 threads: j = t>>3, warp w = t&7
        float v = smax[t];
#pragma unroll
        for (int o = 4; o; o >>= 1)
            v = fmaxf(v, __shfl_xor_sync(0xffffffffu, v, o));
        if ((t & 7) == 0)
            g_partial[(rowbase + (t >> 3)) * CHUNKS + chunk] = v;
    }
    __threadfence();
    __syncthreads();

    if (t == 0) {
        int old = atomicAdd(&g_ctr[grp], 1);
        slast = (old == CHUNKS - 1);
    }
    __syncthreads();

    // ---- Last block of the row-group: reduce 4x16 partials, fixup, out ----
    if (slast && t < CG * CHUNKS) {     // 64 threads: j = t>>4, k = t&15
        int j = t >> 4;
        float v = g_partial[(rowbase + j) * CHUNKS + (t & 15)];
#pragma unroll
        for (int o = 8; o; o >>= 1)
            v = fmaxf(v, __shfl_xor_sync(0xffffffffu, v, o));
        if ((t & 15) == 0)
            out[rowbase + j] = g_nonempty[b] ? v : 0.0f;
        if (t == 0) g_ctr[grp] = 0;     // reset for next graph replay
    }
}

extern "C" void kernel_launch(void* const* d_in, const int* in_sizes, int n_in,
                              void* d_out, int out_size) {
    const float4* x     = (const float4*)d_in[0];
    const int4*   mask4 = (const int4*)d_in[1];
    float*        out   = (float*)d_out;

    fused_kernel<<<NB * (NC / CG) * CHUNKS, THREADS>>>(x, mask4, out);
}